// round 1
// baseline (speedup 1.0000x reference)
#include <cuda_runtime.h>
#include <cuda_bf16.h>
#include <math.h>

#define B_  2
#define S_  2048
#define DM_ 2048
#define H_  16
#define DH_ 128

// ---------------- scratch (device globals: allocation-free) ----------------
__device__ float g_qlin[B_*S_*DM_];        // 32 MB
__device__ float g_kvlin[B_*S_*2*DH_];     // 4 MB
__device__ float g_Q[B_*H_*S_*DH_];        // 32 MB  [B,H,S,D]
__device__ float g_K[B_*S_*DH_];           // 2 MB   [B,S,D]
__device__ float g_V[B_*S_*DH_];           // 2 MB
__device__ float g_ctx[B_*S_*DM_];         // 32 MB  [B*S, H*D]
__device__ float g_qc[S_*64], g_qs[S_*64], g_kc[S_*64], g_ks[S_*64];

// ---------------- rotary tables ----------------
__global__ void rotary_tables() {
    int idx = blockIdx.x*blockDim.x + threadIdx.x;
    if (idx >= S_*64) return;
    int s = idx >> 6, j = idx & 63;
    float inv_freq = powf(10000.0f, -(2.0f*j)/128.0f);
    float pos = (float)s * inv_freq;
    float sb = (2.0f*j + 0.4f*128.0f) / (1.4f*128.0f);
    float power = ((float)s - (float)(S_/2)) / 512.0f;
    float xs = powf(sb, power);
    float c = cosf(pos), sn = sinf(pos);
    g_qc[idx] = c*xs;  g_qs[idx] = sn*xs;
    g_kc[idx] = c/xs;  g_ks[idx] = sn/xs;
}

// ---------------- tiled fp32 GEMM: C[M,N] = A[M,K] @ B[N,K]^T (+bias) ------
__global__ __launch_bounds__(256) void gemm_nt(const float* __restrict__ A,
        const float* __restrict__ Bm, float* __restrict__ C,
        int M, int N, int K, const float* __restrict__ bias) {
    __shared__ float As[16][129];
    __shared__ float Bs[16][129];
    int tid = threadIdx.x;
    int tx = tid & 15, ty = tid >> 4;
    int m0 = blockIdx.y*128, n0 = blockIdx.x*128;
    float acc[8][8];
    #pragma unroll
    for (int i=0;i<8;i++)
        #pragma unroll
        for (int j=0;j<8;j++) acc[i][j]=0.f;

    for (int k0=0;k0<K;k0+=16) {
        #pragma unroll
        for (int it=0; it<8; it++) {
            int i = tid + it*256;
            int r = i >> 4, c = i & 15;
            As[c][r] = A[(size_t)(m0+r)*K + k0+c];
            Bs[c][r] = Bm[(size_t)(n0+r)*K + k0+c];
        }
        __syncthreads();
        #pragma unroll
        for (int k=0;k<16;k++) {
            float a[8], b[8];
            #pragma unroll
            for (int i=0;i<8;i++) a[i]=As[k][ty*8+i];
            #pragma unroll
            for (int j=0;j<8;j++) b[j]=Bs[k][tx*8+j];
            #pragma unroll
            for (int i=0;i<8;i++)
                #pragma unroll
                for (int j=0;j<8;j++) acc[i][j] = fmaf(a[i], b[j], acc[i][j]);
        }
        __syncthreads();
    }
    #pragma unroll
    for (int i=0;i<8;i++) {
        int m = m0+ty*8+i;
        #pragma unroll
        for (int j=0;j<8;j++) {
            int n = n0+tx*8+j;
            float v = acc[i][j];
            if (bias) v += bias[n];
            C[(size_t)m*N+n] = v;
        }
    }
}

// ---------------- rotary apply: Q ----------------
__global__ void rot_q() {
    int idx = blockIdx.x*blockDim.x + threadIdx.x;   // B*S*H*64
    if (idx >= B_*S_*H_*64) return;
    int d = idx & 63;
    int h = (idx >> 6) & 15;
    int s = (idx >> 10) & (S_-1);
    int b = idx >> 21;
    const float sw = 0.08838834764831845f;  // 128^-0.5
    size_t base = ((size_t)(b*S_+s))*DM_ + h*DH_;
    float x1 = g_qlin[base+d], x2 = g_qlin[base+d+64];
    float c = g_qc[s*64+d], sn = g_qs[s*64+d];
    size_t ob = ((size_t)((b*H_+h)*S_+s))*DH_;
    g_Q[ob+d]    = sw*(x1*c - x2*sn);
    g_Q[ob+d+64] = sw*(x2*c + x1*sn);
}

// ---------------- rotary apply: K, copy V ----------------
__global__ void rot_kv() {
    int idx = blockIdx.x*blockDim.x + threadIdx.x;   // B*S*64
    if (idx >= B_*S_*64) return;
    int d = idx & 63;
    int s = (idx >> 6) & (S_-1);
    int b = idx >> 17;
    const float sw = 0.08838834764831845f;
    size_t base = ((size_t)(b*S_+s))*(2*DH_);
    float x1 = g_kvlin[base+d], x2 = g_kvlin[base+d+64];
    float c = g_kc[s*64+d], sn = g_ks[s*64+d];
    size_t ob = ((size_t)(b*S_+s))*DH_;
    g_K[ob+d]    = sw*(x1*c - x2*sn);
    g_K[ob+d+64] = sw*(x2*c + x1*sn);
    g_V[ob+d]    = g_kvlin[base+128+d];
    g_V[ob+d+64] = g_kvlin[base+192+d];
}

// ---------------- flash attention ----------------
// grid: x = q tile (S/64), y = b*H + h.  256 threads, 16x16.
// smem: Qs[128][65], Ks[128][65], Vs[64][128], Ps[64][65]
#define FL_SMEM ((2*128*65 + 64*128 + 64*65)*4)

__global__ __launch_bounds__(256) void flash_attn() {
    extern __shared__ float sm[];
    float* Qs = sm;                    // [128][65] transposed
    float* Ks = Qs + 128*65;           // [128][65] transposed
    float* Vs = Ks + 128*65;           // [64][128]
    float* Ps = Vs + 64*128;           // [64][65]
    int tid = threadIdx.x;
    int tx = tid & 15, ty = tid >> 4;
    int bh = blockIdx.y;
    int b = bh >> 4;
    int h = bh & 15;
    int qt = blockIdx.x;
    int q0 = qt*64;
    const float* Qb = g_Q + (size_t)bh*S_*DH_;
    const float* Kb = g_K + (size_t)b*S_*DH_;
    const float* Vb = g_V + (size_t)b*S_*DH_;

    // load Q tile transposed
    #pragma unroll
    for (int it=0; it<32; it++) {
        int i = tid + it*256;
        int r = i >> 7, d = i & 127;
        Qs[d*65 + r] = Qb[(size_t)(q0+r)*DH_ + d];
    }
    float m[4], l[4], o[4][8];
    #pragma unroll
    for (int i=0;i<4;i++) {
        m[i] = -1e30f; l[i] = 0.f;
        #pragma unroll
        for (int j=0;j<8;j++) o[i][j]=0.f;
    }
    __syncthreads();

    int ntiles = qt + 1;
    for (int t=0; t<ntiles; t++) {
        int j0 = t*64;
        #pragma unroll
        for (int it=0; it<32; it++) {
            int i = tid + it*256;
            int r = i >> 7, d = i & 127;
            float kv = Kb[(size_t)(j0+r)*DH_ + d];
            Ks[d*65 + r] = kv;
            Vs[r*128 + d] = Vb[(size_t)(j0+r)*DH_ + d];
        }
        __syncthreads();

        // S = Q K^T  (4x4 per thread)
        float s[4][4];
        #pragma unroll
        for (int i=0;i<4;i++)
            #pragma unroll
            for (int j=0;j<4;j++) s[i][j]=0.f;
        for (int k=0;k<DH_;k++) {
            float a[4], bb[4];
            #pragma unroll
            for (int i=0;i<4;i++) a[i]=Qs[k*65 + ty*4+i];
            #pragma unroll
            for (int j=0;j<4;j++) bb[j]=Ks[k*65 + tx*4+j];
            #pragma unroll
            for (int i=0;i<4;i++)
                #pragma unroll
                for (int j=0;j<4;j++) s[i][j] = fmaf(a[i], bb[j], s[i][j]);
        }
        if (t == ntiles-1) {
            #pragma unroll
            for (int i=0;i<4;i++) {
                int qr = q0+ty*4+i;
                #pragma unroll
                for (int j=0;j<4;j++)
                    if (j0+tx*4+j > qr) s[i][j] = -1e30f;
            }
        }
        // online softmax, rows grouped over 16 lanes (same ty)
        #pragma unroll
        for (int i=0;i<4;i++) {
            float tm = fmaxf(fmaxf(s[i][0],s[i][1]), fmaxf(s[i][2],s[i][3]));
            #pragma unroll
            for (int off=8; off>=1; off>>=1)
                tm = fmaxf(tm, __shfl_xor_sync(0xffffffffu, tm, off, 16));
            float mn = fmaxf(m[i], tm);
            float c = __expf(m[i]-mn);
            float rs = 0.f;
            #pragma unroll
            for (int j=0;j<4;j++) { s[i][j] = __expf(s[i][j]-mn); rs += s[i][j]; }
            #pragma unroll
            for (int off=8; off>=1; off>>=1)
                rs += __shfl_xor_sync(0xffffffffu, rs, off, 16);
            l[i] = l[i]*c + rs;
            m[i] = mn;
            #pragma unroll
            for (int j=0;j<8;j++) o[i][j] *= c;
            #pragma unroll
            for (int j=0;j<4;j++) Ps[(ty*4+i)*65 + tx*4+j] = s[i][j];
        }
        __syncthreads();
        // O += P @ V
        for (int kc=0;kc<64;kc++) {
            float a[4], bb[8];
            #pragma unroll
            for (int i=0;i<4;i++) a[i]=Ps[(ty*4+i)*65 + kc];
            #pragma unroll
            for (int j=0;j<8;j++) bb[j]=Vs[kc*128 + tx*8+j];
            #pragma unroll
            for (int i=0;i<4;i++)
                #pragma unroll
                for (int j=0;j<8;j++) o[i][j] = fmaf(a[i], bb[j], o[i][j]);
        }
        __syncthreads();
    }
    // write ctx[b*S+s, h*128+d]
    #pragma unroll
    for (int i=0;i<4;i++) {
        float inv = 1.f/l[i];
        int srow = q0+ty*4+i;
        size_t base = ((size_t)(b*S_+srow))*DM_ + h*DH_;
        #pragma unroll
        for (int j=0;j<8;j++)
            g_ctx[base + tx*8+j] = o[i][j]*inv;
    }
}

// ---------------- launch ----------------
extern "C" void kernel_launch(void* const* d_in, const int* in_sizes, int n_in,
                              void* d_out, int out_size) {
    const float* X     = (const float*)d_in[0];   // [2,2048,2048]
    const float* Wq    = (const float*)d_in[1];   // [2048,2048]
    const float* Wkv   = (const float*)d_in[2];   // [256,2048]
    const float* Wproj = (const float*)d_in[3];   // [2048,2048]
    const float* bproj = (const float*)d_in[4];   // [2048]
    float* out = (float*)d_out;                   // [2,2048,2048]

    static int smem_set = 0;
    if (!smem_set) {
        cudaFuncSetAttribute(flash_attn, cudaFuncAttributeMaxDynamicSharedMemorySize, FL_SMEM);
        smem_set = 1;
    }

    float* qlin;  cudaGetSymbolAddress((void**)&qlin,  g_qlin);
    float* kvlin; cudaGetSymbolAddress((void**)&kvlin, g_kvlin);
    float* ctx;   cudaGetSymbolAddress((void**)&ctx,   g_ctx);

    const int M = B_*S_;   // 4096

    rotary_tables<<<(S_*64+255)/256, 256>>>();
    gemm_nt<<<dim3(DM_/128,   M/128), 256>>>(X, Wq,  qlin,  M, DM_,    DM_, nullptr);
    gemm_nt<<<dim3(2*DH_/128, M/128), 256>>>(X, Wkv, kvlin, M, 2*DH_,  DM_, nullptr);
    rot_q <<<(B_*S_*H_*64+255)/256, 256>>>();
    rot_kv<<<(B_*S_*64+255)/256,    256>>>();
    flash_attn<<<dim3(S_/64, B_*H_), 256, FL_SMEM>>>();
    gemm_nt<<<dim3(DM_/128, M/128), 256>>>(ctx, Wproj, out, M, DM_, DM_, bproj);
}

// round 2
// speedup vs baseline: 5.1307x; 5.1307x over previous
#include <cuda_runtime.h>
#include <cuda_bf16.h>
#include <math.h>

#define B_  2
#define S_  2048
#define DM_ 2048
#define H_  16
#define DH_ 128

// ---------------- scratch (device globals: allocation-free) ----------------
__device__ float g_qlin[B_*S_*DM_];
__device__ float g_kvlin[B_*S_*2*DH_];
__device__ float g_Q[B_*H_*S_*DH_];        // [B,H,S,D]
__device__ float g_K[B_*S_*DH_];
__device__ float g_V[B_*S_*DH_];
__device__ float g_ctx[B_*S_*DM_];
__device__ float g_qc[S_*64], g_qs[S_*64], g_kc[S_*64], g_ks[S_*64];

// ---------------- tf32 helpers ----------------
__device__ __forceinline__ unsigned f2tf(float x) {
    unsigned r; asm("cvt.rna.tf32.f32 %0, %1;" : "=r"(r) : "f"(x)); return r;
}
__device__ __forceinline__ float f2tff(float x) { return __uint_as_float(f2tf(x)); }

__device__ __forceinline__ void mma8(float c[4], const unsigned a[4], const unsigned b[2]) {
    asm volatile(
        "mma.sync.aligned.m16n8k8.row.col.f32.tf32.tf32.f32 "
        "{%0,%1,%2,%3},{%4,%5,%6,%7},{%8,%9},{%0,%1,%2,%3};"
        : "+f"(c[0]), "+f"(c[1]), "+f"(c[2]), "+f"(c[3])
        : "r"(a[0]), "r"(a[1]), "r"(a[2]), "r"(a[3]), "r"(b[0]), "r"(b[1]));
}

// ---------------- rotary tables ----------------
__global__ void rotary_tables() {
    int idx = blockIdx.x*blockDim.x + threadIdx.x;
    if (idx >= S_*64) return;
    int s = idx >> 6, j = idx & 63;
    float inv_freq = powf(10000.0f, -(2.0f*j)/128.0f);
    float pos = (float)s * inv_freq;
    float sb = (2.0f*j + 0.4f*128.0f) / (1.4f*128.0f);
    float power = ((float)s - (float)(S_/2)) / 512.0f;
    float xs = powf(sb, power);
    float c = cosf(pos), sn = sinf(pos);
    g_qc[idx] = c*xs;  g_qs[idx] = sn*xs;
    g_kc[idx] = c/xs;  g_ks[idx] = sn/xs;
}

// ---------------- tensor-core GEMM: C[M,N] = A[M,K] @ B[N,K]^T (+bias) ----
// CTA 128x128, BK=32, 8 warps as 2(m)x4(n), warp tile 64x32.
__global__ __launch_bounds__(256) void gemm_nt(const float* __restrict__ A,
        const float* __restrict__ Bm, float* __restrict__ C,
        int M, int N, int K, const float* __restrict__ bias) {
    __shared__ float As[128*36];
    __shared__ float Bs[128*36];
    int tid = threadIdx.x, wid = tid >> 5, lane = tid & 31;
    int g = lane >> 2, t = lane & 3;
    int wm = (wid & 1)*64, wn = (wid >> 1)*32;
    int m0 = blockIdx.y*128, n0 = blockIdx.x*128;
    float acc[4][4][4];
    #pragma unroll
    for (int i=0;i<4;i++)
        #pragma unroll
        for (int j=0;j<4;j++)
            #pragma unroll
            for (int k=0;k<4;k++) acc[i][j][k]=0.f;

    for (int k0 = 0; k0 < K; k0 += 32) {
        #pragma unroll
        for (int it = 0; it < 4; it++) {
            int idx = tid + it*256;
            int r = idx >> 3, c4 = idx & 7;
            float4 av = *(const float4*)&A[(size_t)(m0+r)*K + k0 + c4*4];
            float4 bv = *(const float4*)&Bm[(size_t)(n0+r)*K + k0 + c4*4];
            *(float4*)&As[r*36 + c4*4] =
                make_float4(f2tff(av.x), f2tff(av.y), f2tff(av.z), f2tff(av.w));
            *(float4*)&Bs[r*36 + c4*4] =
                make_float4(f2tff(bv.x), f2tff(bv.y), f2tff(bv.z), f2tff(bv.w));
        }
        __syncthreads();
        #pragma unroll
        for (int kk = 0; kk < 4; kk++) {
            unsigned af[4][4], bf[4][2];
            int col = kk*8 + t;
            #pragma unroll
            for (int mf = 0; mf < 4; mf++) {
                int row = wm + mf*16 + g;
                af[mf][0] = __float_as_uint(As[row*36 + col]);
                af[mf][1] = __float_as_uint(As[(row+8)*36 + col]);
                af[mf][2] = __float_as_uint(As[row*36 + col + 4]);
                af[mf][3] = __float_as_uint(As[(row+8)*36 + col + 4]);
            }
            #pragma unroll
            for (int nf = 0; nf < 4; nf++) {
                int nr = wn + nf*8 + g;
                bf[nf][0] = __float_as_uint(Bs[nr*36 + col]);
                bf[nf][1] = __float_as_uint(Bs[nr*36 + col + 4]);
            }
            #pragma unroll
            for (int mf = 0; mf < 4; mf++)
                #pragma unroll
                for (int nf = 0; nf < 4; nf++)
                    mma8(acc[mf][nf], af[mf], bf[nf]);
        }
        __syncthreads();
    }
    #pragma unroll
    for (int mf = 0; mf < 4; mf++) {
        #pragma unroll
        for (int nf = 0; nf < 4; nf++) {
            int row = m0 + wm + mf*16 + g;
            int col = n0 + wn + nf*8 + 2*t;
            float b0 = bias ? bias[col]   : 0.f;
            float b1 = bias ? bias[col+1] : 0.f;
            *(float2*)&C[(size_t)row*N + col] =
                make_float2(acc[mf][nf][0]+b0, acc[mf][nf][1]+b1);
            *(float2*)&C[(size_t)(row+8)*N + col] =
                make_float2(acc[mf][nf][2]+b0, acc[mf][nf][3]+b1);
        }
    }
}

// ---------------- rotary apply: Q ----------------
__global__ void rot_q() {
    int idx = blockIdx.x*blockDim.x + threadIdx.x;   // B*S*H*64
    if (idx >= B_*S_*H_*64) return;
    int d = idx & 63;
    int h = (idx >> 6) & 15;
    int s = (idx >> 10) & (S_-1);
    int b = idx >> 21;
    const float sw = 0.08838834764831845f;  // 128^-0.5
    size_t base = ((size_t)(b*S_+s))*DM_ + h*DH_;
    float x1 = g_qlin[base+d], x2 = g_qlin[base+d+64];
    float c = g_qc[s*64+d], sn = g_qs[s*64+d];
    size_t ob = ((size_t)((b*H_+h)*S_+s))*DH_;
    g_Q[ob+d]    = sw*(x1*c - x2*sn);
    g_Q[ob+d+64] = sw*(x2*c + x1*sn);
}

// ---------------- rotary apply: K, copy V ----------------
__global__ void rot_kv() {
    int idx = blockIdx.x*blockDim.x + threadIdx.x;   // B*S*64
    if (idx >= B_*S_*64) return;
    int d = idx & 63;
    int s = (idx >> 6) & (S_-1);
    int b = idx >> 17;
    const float sw = 0.08838834764831845f;
    size_t base = ((size_t)(b*S_+s))*(2*DH_);
    float x1 = g_kvlin[base+d], x2 = g_kvlin[base+d+64];
    float c = g_kc[s*64+d], sn = g_ks[s*64+d];
    size_t ob = ((size_t)(b*S_+s))*DH_;
    g_K[ob+d]    = sw*(x1*c - x2*sn);
    g_K[ob+d+64] = sw*(x2*c + x1*sn);
    g_V[ob+d]    = g_kvlin[base+128+d];
    g_V[ob+d+64] = g_kvlin[base+192+d];
}

// ---------------- flash attention (tensor cores) ----------------
// BQ=128, BKV=64, D=128. 8 warps; warp w owns rows [16w,16w+16).
// smem: Ks[64][132], Vs[64][136], Ps[128][68]  (all tf32 bits, pads -> no bank conflicts)
#define FL_SMEM ((64*132 + 64*136 + 128*68)*4)

__global__ __launch_bounds__(256) void flash_attn() {
    extern __shared__ float sm[];
    float* Ks = sm;
    float* Vs = Ks + 64*132;
    float* Ps = Vs + 64*136;
    int tid = threadIdx.x;
    int wid = tid >> 5, lane = tid & 31;
    int g = lane >> 2, t = lane & 3;
    int bh = blockIdx.y, b = bh >> 4, h = bh & 15;
    int q0 = blockIdx.x * 128;
    int wrow = wid * 16;
    const float* Qb = g_Q + (size_t)bh * S_ * DH_;
    const float* Kb = g_K + (size_t)b  * S_ * DH_;
    const float* Vb = g_V + (size_t)b  * S_ * DH_;

    // Q as persistent tf32 A-fragments
    unsigned qa[16][4];
    {
        int r0 = q0 + wrow + g;
        #pragma unroll
        for (int kf = 0; kf < 16; kf++) {
            int c0 = kf*8 + t;
            qa[kf][0] = f2tf(Qb[(size_t)r0*DH_ + c0]);
            qa[kf][1] = f2tf(Qb[(size_t)(r0+8)*DH_ + c0]);
            qa[kf][2] = f2tf(Qb[(size_t)r0*DH_ + c0+4]);
            qa[kf][3] = f2tf(Qb[(size_t)(r0+8)*DH_ + c0+4]);
        }
    }
    float oacc[16][4];
    #pragma unroll
    for (int i=0;i<16;i++)
        #pragma unroll
        for (int j=0;j<4;j++) oacc[i][j]=0.f;
    float mrow[2] = {-1e30f,-1e30f}, lrow[2] = {0.f,0.f};

    int ntiles = 2*blockIdx.x + 2;
    for (int kt = 0; kt < ntiles; kt++) {
        int j0 = kt * 64;
        // load K,V tiles (tf32-converted)
        #pragma unroll
        for (int it = 0; it < 8; it++) {
            int idx = tid + it*256;
            int r = idx >> 5, c4 = idx & 31;
            float4 kv = *(const float4*)&Kb[(size_t)(j0+r)*DH_ + c4*4];
            float4 vv = *(const float4*)&Vb[(size_t)(j0+r)*DH_ + c4*4];
            *(float4*)&Ks[r*132 + c4*4] =
                make_float4(f2tff(kv.x), f2tff(kv.y), f2tff(kv.z), f2tff(kv.w));
            *(float4*)&Vs[r*136 + c4*4] =
                make_float4(f2tff(vv.x), f2tff(vv.y), f2tff(vv.z), f2tff(vv.w));
        }
        __syncthreads();

        // S = Q @ K^T : warp computes 16x64
        float s[8][4];
        #pragma unroll
        for (int i=0;i<8;i++)
            #pragma unroll
            for (int j=0;j<4;j++) s[i][j]=0.f;
        #pragma unroll
        for (int kf = 0; kf < 16; kf++) {
            #pragma unroll
            for (int nf = 0; nf < 8; nf++) {
                unsigned bfr[2];
                bfr[0] = __float_as_uint(Ks[(nf*8+g)*132 + kf*8 + t]);
                bfr[1] = __float_as_uint(Ks[(nf*8+g)*132 + kf*8 + t + 4]);
                mma8(s[nf], qa[kf], bfr);
            }
        }
        // causal mask (only tiles intersecting the diagonal of this warp's rows)
        if (j0 + 63 > q0 + wrow) {
            int r0 = q0 + wrow + g;
            #pragma unroll
            for (int nf = 0; nf < 8; nf++) {
                int c0 = j0 + nf*8 + 2*t;
                if (c0   > r0)   s[nf][0] = -1e30f;
                if (c0+1 > r0)   s[nf][1] = -1e30f;
                if (c0   > r0+8) s[nf][2] = -1e30f;
                if (c0+1 > r0+8) s[nf][3] = -1e30f;
            }
        }
        // online softmax, fully warp-local (quad reduce over lane%4)
        #pragma unroll
        for (int rr = 0; rr < 2; rr++) {
            float mx = -1e30f;
            #pragma unroll
            for (int nf = 0; nf < 8; nf++)
                mx = fmaxf(mx, fmaxf(s[nf][2*rr], s[nf][2*rr+1]));
            mx = fmaxf(mx, __shfl_xor_sync(0xffffffffu, mx, 1));
            mx = fmaxf(mx, __shfl_xor_sync(0xffffffffu, mx, 2));
            float mn = fmaxf(mrow[rr], mx);
            float corr = __expf(mrow[rr] - mn);
            mrow[rr] = mn;
            float rs = 0.f;
            #pragma unroll
            for (int nf = 0; nf < 8; nf++) {
                float e0 = __expf(s[nf][2*rr]   - mn);
                float e1 = __expf(s[nf][2*rr+1] - mn);
                s[nf][2*rr] = e0; s[nf][2*rr+1] = e1;
                rs += e0 + e1;
            }
            rs += __shfl_xor_sync(0xffffffffu, rs, 1);
            rs += __shfl_xor_sync(0xffffffffu, rs, 2);
            lrow[rr] = lrow[rr]*corr + rs;
            #pragma unroll
            for (int nf = 0; nf < 16; nf++) {
                oacc[nf][2*rr]   *= corr;
                oacc[nf][2*rr+1] *= corr;
            }
        }
        // P -> smem (warp-private rows)
        {
            int pr = wrow + g;
            #pragma unroll
            for (int nf = 0; nf < 8; nf++) {
                int pc = nf*8 + 2*t;
                Ps[pr*68 + pc]       = f2tff(s[nf][0]);
                Ps[pr*68 + pc+1]     = f2tff(s[nf][1]);
                Ps[(pr+8)*68 + pc]   = f2tff(s[nf][2]);
                Ps[(pr+8)*68 + pc+1] = f2tff(s[nf][3]);
            }
        }
        __syncwarp();
        // O += P @ V
        #pragma unroll
        for (int kf = 0; kf < 8; kf++) {
            unsigned pa[4];
            int pr = wrow + g, pc = kf*8 + t;
            pa[0] = __float_as_uint(Ps[pr*68 + pc]);
            pa[1] = __float_as_uint(Ps[(pr+8)*68 + pc]);
            pa[2] = __float_as_uint(Ps[pr*68 + pc+4]);
            pa[3] = __float_as_uint(Ps[(pr+8)*68 + pc+4]);
            #pragma unroll
            for (int nf = 0; nf < 16; nf++) {
                unsigned bfr[2];
                bfr[0] = __float_as_uint(Vs[(kf*8+t)*136   + nf*8 + g]);
                bfr[1] = __float_as_uint(Vs[(kf*8+t+4)*136 + nf*8 + g]);
                mma8(oacc[nf], pa, bfr);
            }
        }
        __syncthreads();
    }
    // write ctx
    #pragma unroll
    for (int rr = 0; rr < 2; rr++) {
        float inv = 1.f / lrow[rr];
        int row = q0 + wrow + g + 8*rr;
        size_t base = ((size_t)(b*S_ + row))*DM_ + h*DH_;
        #pragma unroll
        for (int nf = 0; nf < 16; nf++) {
            *(float2*)&g_ctx[base + nf*8 + 2*t] =
                make_float2(oacc[nf][2*rr]*inv, oacc[nf][2*rr+1]*inv);
        }
    }
}

// ---------------- launch ----------------
extern "C" void kernel_launch(void* const* d_in, const int* in_sizes, int n_in,
                              void* d_out, int out_size) {
    const float* X     = (const float*)d_in[0];
    const float* Wq    = (const float*)d_in[1];
    const float* Wkv   = (const float*)d_in[2];
    const float* Wproj = (const float*)d_in[3];
    const float* bproj = (const float*)d_in[4];
    float* out = (float*)d_out;

    static int smem_set = 0;
    if (!smem_set) {
        cudaFuncSetAttribute(flash_attn, cudaFuncAttributeMaxDynamicSharedMemorySize, FL_SMEM);
        smem_set = 1;
    }

    float* qlin;  cudaGetSymbolAddress((void**)&qlin,  g_qlin);
    float* kvlin; cudaGetSymbolAddress((void**)&kvlin, g_kvlin);
    float* ctx;   cudaGetSymbolAddress((void**)&ctx,   g_ctx);

    const int M = B_*S_;   // 4096

    rotary_tables<<<(S_*64+255)/256, 256>>>();
    gemm_nt<<<dim3(DM_/128,   M/128), 256>>>(X, Wq,  qlin,  M, DM_,   DM_, nullptr);
    gemm_nt<<<dim3(2*DH_/128, M/128), 256>>>(X, Wkv, kvlin, M, 2*DH_, DM_, nullptr);
    rot_q <<<(B_*S_*H_*64+255)/256, 256>>>();
    rot_kv<<<(B_*S_*64+255)/256,    256>>>();
    flash_attn<<<dim3(S_/128, B_*H_), 256, FL_SMEM>>>();
    gemm_nt<<<dim3(DM_/128, M/128), 256>>>(ctx, Wproj, out, M, DM_, DM_, bproj);
}

// round 3
// speedup vs baseline: 5.3231x; 1.0375x over previous
#include <cuda_runtime.h>
#include <cuda_bf16.h>
#include <math.h>

#define B_  2
#define S_  2048
#define DM_ 2048
#define H_  16
#define DH_ 128

// ---------------- scratch (device globals: allocation-free) ----------------
__device__ float g_xt[B_*S_*DM_];          // tf32-rounded X
__device__ float g_wqt[DM_*DM_];           // tf32-rounded Wq
__device__ float g_wkvt[2*DH_*DM_];        // tf32-rounded Wkv
__device__ float g_wprojt[DM_*DM_];        // tf32-rounded Wproj
__device__ float g_qlin[B_*S_*DM_];
__device__ float g_kvlin[B_*S_*2*DH_];
__device__ float g_Q[B_*H_*S_*DH_];        // [B,H,S,D] tf32-rounded
__device__ float g_K[B_*S_*DH_];           // tf32-rounded
__device__ float g_V[B_*S_*DH_];           // tf32-rounded
__device__ float g_ctx[B_*S_*DM_];         // tf32-rounded
__device__ float g_qc[S_*64], g_qs[S_*64], g_kc[S_*64], g_ks[S_*64];

// ---------------- tf32 / async helpers ----------------
__device__ __forceinline__ unsigned f2tf(float x) {
    unsigned r; asm("cvt.rna.tf32.f32 %0, %1;" : "=r"(r) : "f"(x)); return r;
}
__device__ __forceinline__ float f2tff(float x) { return __uint_as_float(f2tf(x)); }

__device__ __forceinline__ void mma8(float c[4], const unsigned a[4], const unsigned b[2]) {
    asm volatile(
        "mma.sync.aligned.m16n8k8.row.col.f32.tf32.tf32.f32 "
        "{%0,%1,%2,%3},{%4,%5,%6,%7},{%8,%9},{%0,%1,%2,%3};"
        : "+f"(c[0]), "+f"(c[1]), "+f"(c[2]), "+f"(c[3])
        : "r"(a[0]), "r"(a[1]), "r"(a[2]), "r"(a[3]), "r"(b[0]), "r"(b[1]));
}

__device__ __forceinline__ void cpasync16(void* s, const void* g) {
    unsigned sa = (unsigned)__cvta_generic_to_shared(s);
    asm volatile("cp.async.cg.shared.global [%0], [%1], 16;" :: "r"(sa), "l"(g));
}
#define CP_COMMIT() asm volatile("cp.async.commit_group;" ::: "memory")
#define CP_WAIT(n)  asm volatile("cp.async.wait_group %0;" :: "n"(n) : "memory")

// ---------------- pre-round to tf32 ----------------
__global__ void round_tf32(const float4* __restrict__ src, float4* __restrict__ dst, int n4) {
    int i = blockIdx.x*blockDim.x + threadIdx.x;
    if (i >= n4) return;
    float4 v = src[i];
    dst[i] = make_float4(f2tff(v.x), f2tff(v.y), f2tff(v.z), f2tff(v.w));
}

// ---------------- rotary tables ----------------
__global__ void rotary_tables() {
    int idx = blockIdx.x*blockDim.x + threadIdx.x;
    if (idx >= S_*64) return;
    int s = idx >> 6, j = idx & 63;
    float inv_freq = powf(10000.0f, -(2.0f*j)/128.0f);
    float pos = (float)s * inv_freq;
    float sb = (2.0f*j + 0.4f*128.0f) / (1.4f*128.0f);
    float power = ((float)s - (float)(S_/2)) / 512.0f;
    float xs = powf(sb, power);
    float c = cosf(pos), sn = sinf(pos);
    g_qc[idx] = c*xs;  g_qs[idx] = sn*xs;
    g_kc[idx] = c/xs;  g_ks[idx] = sn/xs;
}

// ---------------- tensor-core GEMM: C = A @ B^T (+bias), cp.async 2-stage --
// CTA 128x128, BK=32, 8 warps as 2(m)x4(n), warp tile 64x32. A,B pre-rounded tf32.
#define GSTG (128*36)
#define G_SMEM (4*GSTG*4)

__global__ __launch_bounds__(256) void gemm_nt(const float* __restrict__ A,
        const float* __restrict__ Bm, float* __restrict__ C,
        int M, int N, int K, const float* __restrict__ bias) {
    extern __shared__ float smg[];
    float* As = smg;
    float* Bs = smg + 2*GSTG;
    int tid = threadIdx.x, wid = tid >> 5, lane = tid & 31;
    int g = lane >> 2, t = lane & 3;
    int wm = (wid & 1)*64, wn = (wid >> 1)*32;
    int m0 = blockIdx.y*128, n0 = blockIdx.x*128;
    float acc[4][4][4];
    #pragma unroll
    for (int i=0;i<4;i++)
        #pragma unroll
        for (int j=0;j<4;j++)
            #pragma unroll
            for (int k=0;k<4;k++) acc[i][j][k]=0.f;

    int lr = tid >> 3, lc = (tid & 7)*4;   // load row/col within tile

    // prefetch tile 0
    #pragma unroll
    for (int it = 0; it < 4; it++) {
        int r = lr + it*32;
        cpasync16(&As[r*36 + lc], &A[(size_t)(m0+r)*K + lc]);
        cpasync16(&Bs[r*36 + lc], &Bm[(size_t)(n0+r)*K + lc]);
    }
    CP_COMMIT();

    int T = K >> 5;
    for (int tt = 0; tt < T; tt++) {
        if (tt+1 < T) {
            int k0 = (tt+1) << 5, stg = (tt+1) & 1;
            float* A_s = As + stg*GSTG; float* B_s = Bs + stg*GSTG;
            #pragma unroll
            for (int it = 0; it < 4; it++) {
                int r = lr + it*32;
                cpasync16(&A_s[r*36 + lc], &A[(size_t)(m0+r)*K + k0 + lc]);
                cpasync16(&B_s[r*36 + lc], &Bm[(size_t)(n0+r)*K + k0 + lc]);
            }
            CP_COMMIT();
            CP_WAIT(1);
        } else {
            CP_WAIT(0);
        }
        __syncthreads();
        const float* A_s = As + (tt&1)*GSTG;
        const float* B_s = Bs + (tt&1)*GSTG;
        #pragma unroll
        for (int kk = 0; kk < 4; kk++) {
            unsigned af[4][4], bf[4][2];
            int col = kk*8 + t;
            #pragma unroll
            for (int mf = 0; mf < 4; mf++) {
                int row = wm + mf*16 + g;
                af[mf][0] = __float_as_uint(A_s[row*36 + col]);
                af[mf][1] = __float_as_uint(A_s[(row+8)*36 + col]);
                af[mf][2] = __float_as_uint(A_s[row*36 + col + 4]);
                af[mf][3] = __float_as_uint(A_s[(row+8)*36 + col + 4]);
            }
            #pragma unroll
            for (int nf = 0; nf < 4; nf++) {
                int nr = wn + nf*8 + g;
                bf[nf][0] = __float_as_uint(B_s[nr*36 + col]);
                bf[nf][1] = __float_as_uint(B_s[nr*36 + col + 4]);
            }
            #pragma unroll
            for (int mf = 0; mf < 4; mf++)
                #pragma unroll
                for (int nf = 0; nf < 4; nf++)
                    mma8(acc[mf][nf], af[mf], bf[nf]);
        }
        __syncthreads();
    }
    #pragma unroll
    for (int mf = 0; mf < 4; mf++) {
        #pragma unroll
        for (int nf = 0; nf < 4; nf++) {
            int row = m0 + wm + mf*16 + g;
            int col = n0 + wn + nf*8 + 2*t;
            float b0 = bias ? bias[col]   : 0.f;
            float b1 = bias ? bias[col+1] : 0.f;
            *(float2*)&C[(size_t)row*N + col] =
                make_float2(acc[mf][nf][0]+b0, acc[mf][nf][1]+b1);
            *(float2*)&C[(size_t)(row+8)*N + col] =
                make_float2(acc[mf][nf][2]+b0, acc[mf][nf][3]+b1);
        }
    }
}

// ---------------- rotary apply: Q (stores tf32-rounded) ----------------
__global__ void rot_q() {
    int idx = blockIdx.x*blockDim.x + threadIdx.x;   // B*S*H*64
    if (idx >= B_*S_*H_*64) return;
    int d = idx & 63;
    int h = (idx >> 6) & 15;
    int s = (idx >> 10) & (S_-1);
    int b = idx >> 21;
    const float sw = 0.08838834764831845f;  // 128^-0.5
    size_t base = ((size_t)(b*S_+s))*DM_ + h*DH_;
    float x1 = g_qlin[base+d], x2 = g_qlin[base+d+64];
    float c = g_qc[s*64+d], sn = g_qs[s*64+d];
    size_t ob = ((size_t)((b*H_+h)*S_+s))*DH_;
    g_Q[ob+d]    = f2tff(sw*(x1*c - x2*sn));
    g_Q[ob+d+64] = f2tff(sw*(x2*c + x1*sn));
}

// ---------------- rotary apply: K, copy V (stores tf32-rounded) ------------
__global__ void rot_kv() {
    int idx = blockIdx.x*blockDim.x + threadIdx.x;   // B*S*64
    if (idx >= B_*S_*64) return;
    int d = idx & 63;
    int s = (idx >> 6) & (S_-1);
    int b = idx >> 17;
    const float sw = 0.08838834764831845f;
    size_t base = ((size_t)(b*S_+s))*(2*DH_);
    float x1 = g_kvlin[base+d], x2 = g_kvlin[base+d+64];
    float c = g_kc[s*64+d], sn = g_ks[s*64+d];
    size_t ob = ((size_t)(b*S_+s))*DH_;
    g_K[ob+d]    = f2tff(sw*(x1*c - x2*sn));
    g_K[ob+d+64] = f2tff(sw*(x2*c + x1*sn));
    g_V[ob+d]    = f2tff(g_kvlin[base+128+d]);
    g_V[ob+d+64] = f2tff(g_kvlin[base+192+d]);
}

// ---------------- flash attention (tensor cores, cp.async 2-stage) ---------
// BQ=128, BKV=64, D=128. 8 warps; warp w owns rows [16w,16w+16).
// smem: 2 stages of (Ks[64][132] + Vs[64][136]) + Ps[128][68]
#define KVSTG (64*132 + 64*136)
#define FL_SMEM ((2*KVSTG + 128*68)*4)

__global__ __launch_bounds__(256) void flash_attn() {
    extern __shared__ float smf[];
    float* Ps = smf + 2*KVSTG;
    int tid = threadIdx.x;
    int wid = tid >> 5, lane = tid & 31;
    int g = lane >> 2, t = lane & 3;
    int bh = blockIdx.y, b = bh >> 4, h = bh & 15;
    int qt = gridDim.x - 1 - blockIdx.x;   // longest work first
    int q0 = qt * 128;
    int wrow = wid * 16;
    const float* Qb = g_Q + (size_t)bh * S_ * DH_;
    const float* Kb = g_K + (size_t)b  * S_ * DH_;
    const float* Vb = g_V + (size_t)b  * S_ * DH_;

    int lr = tid >> 2, lc = (tid & 3)*32;  // kv load coords: 64 rows, 128 cols

    // Q as persistent tf32 A-fragments (pre-rounded in g_Q)
    unsigned qa[16][4];
    {
        int r0 = q0 + wrow + g;
        #pragma unroll
        for (int kf = 0; kf < 16; kf++) {
            int c0 = kf*8 + t;
            qa[kf][0] = __float_as_uint(Qb[(size_t)r0*DH_ + c0]);
            qa[kf][1] = __float_as_uint(Qb[(size_t)(r0+8)*DH_ + c0]);
            qa[kf][2] = __float_as_uint(Qb[(size_t)r0*DH_ + c0+4]);
            qa[kf][3] = __float_as_uint(Qb[(size_t)(r0+8)*DH_ + c0+4]);
        }
    }
    float oacc[16][4];
    #pragma unroll
    for (int i=0;i<16;i++)
        #pragma unroll
        for (int j=0;j<4;j++) oacc[i][j]=0.f;
    float mrow[2] = {-1e30f,-1e30f}, lrow[2] = {0.f,0.f};

    int ntiles = 2*qt + 2;
    // prefetch kv tile 0
    {
        float* Ks0 = smf; float* Vs0 = smf + 64*132;
        #pragma unroll
        for (int c8 = 0; c8 < 8; c8++) {
            cpasync16(&Ks0[lr*132 + lc + c8*4], &Kb[(size_t)lr*DH_ + lc + c8*4]);
            cpasync16(&Vs0[lr*136 + lc + c8*4], &Vb[(size_t)lr*DH_ + lc + c8*4]);
        }
        CP_COMMIT();
    }

    for (int kt = 0; kt < ntiles; kt++) {
        if (kt+1 < ntiles) {
            int j0n = (kt+1)*64;
            float* Ksn = smf + ((kt+1)&1)*KVSTG;
            float* Vsn = Ksn + 64*132;
            #pragma unroll
            for (int c8 = 0; c8 < 8; c8++) {
                cpasync16(&Ksn[lr*132 + lc + c8*4], &Kb[(size_t)(j0n+lr)*DH_ + lc + c8*4]);
                cpasync16(&Vsn[lr*136 + lc + c8*4], &Vb[(size_t)(j0n+lr)*DH_ + lc + c8*4]);
            }
            CP_COMMIT();
            CP_WAIT(1);
        } else {
            CP_WAIT(0);
        }
        __syncthreads();
        const float* Ks = smf + (kt&1)*KVSTG;
        const float* Vs = Ks + 64*132;
        int j0 = kt * 64;

        // S = Q @ K^T : warp computes 16x64
        float s[8][4];
        #pragma unroll
        for (int i=0;i<8;i++)
            #pragma unroll
            for (int j=0;j<4;j++) s[i][j]=0.f;
        #pragma unroll
        for (int kf = 0; kf < 16; kf++) {
            #pragma unroll
            for (int nf = 0; nf < 8; nf++) {
                unsigned bfr[2];
                bfr[0] = __float_as_uint(Ks[(nf*8+g)*132 + kf*8 + t]);
                bfr[1] = __float_as_uint(Ks[(nf*8+g)*132 + kf*8 + t + 4]);
                mma8(s[nf], qa[kf], bfr);
            }
        }
        // causal mask
        if (j0 + 63 > q0 + wrow) {
            int r0 = q0 + wrow + g;
            #pragma unroll
            for (int nf = 0; nf < 8; nf++) {
                int c0 = j0 + nf*8 + 2*t;
                if (c0   > r0)   s[nf][0] = -1e30f;
                if (c0+1 > r0)   s[nf][1] = -1e30f;
                if (c0   > r0+8) s[nf][2] = -1e30f;
                if (c0+1 > r0+8) s[nf][3] = -1e30f;
            }
        }
        // online softmax (warp-local quad reductions)
        #pragma unroll
        for (int rr = 0; rr < 2; rr++) {
            float mx = -1e30f;
            #pragma unroll
            for (int nf = 0; nf < 8; nf++)
                mx = fmaxf(mx, fmaxf(s[nf][2*rr], s[nf][2*rr+1]));
            mx = fmaxf(mx, __shfl_xor_sync(0xffffffffu, mx, 1));
            mx = fmaxf(mx, __shfl_xor_sync(0xffffffffu, mx, 2));
            float mn = fmaxf(mrow[rr], mx);
            float corr = __expf(mrow[rr] - mn);
            mrow[rr] = mn;
            float rs = 0.f;
            #pragma unroll
            for (int nf = 0; nf < 8; nf++) {
                float e0 = __expf(s[nf][2*rr]   - mn);
                float e1 = __expf(s[nf][2*rr+1] - mn);
                s[nf][2*rr] = e0; s[nf][2*rr+1] = e1;
                rs += e0 + e1;
            }
            rs += __shfl_xor_sync(0xffffffffu, rs, 1);
            rs += __shfl_xor_sync(0xffffffffu, rs, 2);
            lrow[rr] = lrow[rr]*corr + rs;
            #pragma unroll
            for (int nf = 0; nf < 16; nf++) {
                oacc[nf][2*rr]   *= corr;
                oacc[nf][2*rr+1] *= corr;
            }
        }
        // P -> smem (warp-private rows)
        {
            int pr = wrow + g;
            #pragma unroll
            for (int nf = 0; nf < 8; nf++) {
                int pc = nf*8 + 2*t;
                Ps[pr*68 + pc]       = f2tff(s[nf][0]);
                Ps[pr*68 + pc+1]     = f2tff(s[nf][1]);
                Ps[(pr+8)*68 + pc]   = f2tff(s[nf][2]);
                Ps[(pr+8)*68 + pc+1] = f2tff(s[nf][3]);
            }
        }
        __syncwarp();
        // O += P @ V
        #pragma unroll
        for (int kf = 0; kf < 8; kf++) {
            unsigned pa[4];
            int pr = wrow + g, pc = kf*8 + t;
            pa[0] = __float_as_uint(Ps[pr*68 + pc]);
            pa[1] = __float_as_uint(Ps[(pr+8)*68 + pc]);
            pa[2] = __float_as_uint(Ps[pr*68 + pc+4]);
            pa[3] = __float_as_uint(Ps[(pr+8)*68 + pc+4]);
            #pragma unroll
            for (int nf = 0; nf < 16; nf++) {
                unsigned bfr[2];
                bfr[0] = __float_as_uint(Vs[(kf*8+t)*136   + nf*8 + g]);
                bfr[1] = __float_as_uint(Vs[(kf*8+t+4)*136 + nf*8 + g]);
                mma8(oacc[nf], pa, bfr);
            }
        }
        __syncthreads();
    }
    // write ctx (tf32-rounded: feeds out-proj GEMM directly)
    #pragma unroll
    for (int rr = 0; rr < 2; rr++) {
        float inv = 1.f / lrow[rr];
        int row = q0 + wrow + g + 8*rr;
        size_t base = ((size_t)(b*S_ + row))*DM_ + h*DH_;
        #pragma unroll
        for (int nf = 0; nf < 16; nf++) {
            *(float2*)&g_ctx[base + nf*8 + 2*t] =
                make_float2(f2tff(oacc[nf][2*rr]*inv), f2tff(oacc[nf][2*rr+1]*inv));
        }
    }
}

// ---------------- launch ----------------
extern "C" void kernel_launch(void* const* d_in, const int* in_sizes, int n_in,
                              void* d_out, int out_size) {
    const float* X     = (const float*)d_in[0];
    const float* Wq    = (const float*)d_in[1];
    const float* Wkv   = (const float*)d_in[2];
    const float* Wproj = (const float*)d_in[3];
    const float* bproj = (const float*)d_in[4];
    float* out = (float*)d_out;

    static int attr_set = 0;
    if (!attr_set) {
        cudaFuncSetAttribute(flash_attn, cudaFuncAttributeMaxDynamicSharedMemorySize, FL_SMEM);
        cudaFuncSetAttribute(gemm_nt,    cudaFuncAttributeMaxDynamicSharedMemorySize, G_SMEM);
        attr_set = 1;
    }

    float* xt;    cudaGetSymbolAddress((void**)&xt,    g_xt);
    float* wqt;   cudaGetSymbolAddress((void**)&wqt,   g_wqt);
    float* wkvt;  cudaGetSymbolAddress((void**)&wkvt,  g_wkvt);
    float* wpjt;  cudaGetSymbolAddress((void**)&wpjt,  g_wprojt);
    float* qlin;  cudaGetSymbolAddress((void**)&qlin,  g_qlin);
    float* kvlin; cudaGetSymbolAddress((void**)&kvlin, g_kvlin);
    float* ctx;   cudaGetSymbolAddress((void**)&ctx,   g_ctx);

    const int M = B_*S_;   // 4096

    round_tf32<<<(B_*S_*DM_/4+255)/256, 256>>>((const float4*)X,     (float4*)xt,   B_*S_*DM_/4);
    round_tf32<<<(DM_*DM_/4+255)/256,   256>>>((const float4*)Wq,    (float4*)wqt,  DM_*DM_/4);
    round_tf32<<<(2*DH_*DM_/4+255)/256, 256>>>((const float4*)Wkv,   (float4*)wkvt, 2*DH_*DM_/4);
    round_tf32<<<(DM_*DM_/4+255)/256,   256>>>((const float4*)Wproj, (float4*)wpjt, DM_*DM_/4);
    rotary_tables<<<(S_*64+255)/256, 256>>>();

    gemm_nt<<<dim3(DM_/128,   M/128), 256, G_SMEM>>>(xt, wqt,  qlin,  M, DM_,   DM_, nullptr);
    gemm_nt<<<dim3(2*DH_/128, M/128), 256, G_SMEM>>>(xt, wkvt, kvlin, M, 2*DH_, DM_, nullptr);
    rot_q <<<(B_*S_*H_*64+255)/256, 256>>>();
    rot_kv<<<(B_*S_*64+255)/256,    256>>>();
    flash_attn<<<dim3(S_/128, B_*H_), 256, FL_SMEM>>>();
    gemm_nt<<<dim3(DM_/128, M/128), 256, G_SMEM>>>(ctx, wpjt, out, M, DM_, DM_, bproj);
}

// round 5
// speedup vs baseline: 9.0972x; 1.7090x over previous
#include <cuda_runtime.h>
#include <cuda_fp16.h>
#include <math.h>
#include <stdint.h>

#define B_  2
#define S_  2048
#define DM_ 2048
#define H_  16
#define DH_ 128

// ---------------- scratch (device globals: allocation-free) ----------------
__device__ __half g_Xh[B_*S_*DM_];
__device__ __half g_Wqh[DM_*DM_];
__device__ __half g_Wkvh[2*DH_*DM_];
__device__ __half g_Wph[DM_*DM_];
__device__ float  g_qlin[B_*S_*DM_];
__device__ float  g_kvlin[B_*S_*2*DH_];
__device__ __half g_Qh[B_*H_*S_*DH_];      // [B,H,S,D]
__device__ __half g_Kh[B_*S_*DH_];         // [B,S,D]
__device__ __half g_Vt[B_*DH_*S_];         // [B,D,S]  (transposed V)
__device__ __half g_ctxh[B_*S_*DM_];       // [B*S, H*D]
__device__ float  g_qc[S_*64], g_qs[S_*64], g_kc[S_*64], g_ks[S_*64];

// ---------------- helpers ----------------
__device__ __forceinline__ void mma_h(float c[4], const unsigned a[4], const unsigned b[2]) {
    asm volatile(
        "mma.sync.aligned.m16n8k16.row.col.f32.f16.f16.f32 "
        "{%0,%1,%2,%3},{%4,%5,%6,%7},{%8,%9},{%0,%1,%2,%3};"
        : "+f"(c[0]), "+f"(c[1]), "+f"(c[2]), "+f"(c[3])
        : "r"(a[0]), "r"(a[1]), "r"(a[2]), "r"(a[3]), "r"(b[0]), "r"(b[1]));
}
__device__ __forceinline__ void cpasync16(void* s, const void* g) {
    unsigned sa = (unsigned)__cvta_generic_to_shared(s);
    asm volatile("cp.async.cg.shared.global [%0], [%1], 16;" :: "r"(sa), "l"(g));
}
#define CP_COMMIT() asm volatile("cp.async.commit_group;" ::: "memory")
#define CP_WAIT(n)  asm volatile("cp.async.wait_group %0;" :: "n"(n) : "memory")
__device__ __forceinline__ unsigned packh2(float x, float y) {
    __half2 h = __floats2half2_rn(x, y);
    return *(unsigned*)&h;
}

// ---------------- fp32 -> fp16 convert ----------------
__global__ void cvt_half(const float4* __restrict__ src, __half2* __restrict__ dst, int n4) {
    int i = blockIdx.x*1024 + threadIdx.x;
    #pragma unroll
    for (int k = 0; k < 4; k++) {
        int j = i + k*256;
        if (j < n4) {
            float4 v = src[j];
            dst[2*j]   = __floats2half2_rn(v.x, v.y);
            dst[2*j+1] = __floats2half2_rn(v.z, v.w);
        }
    }
}

// ---------------- rotary tables ----------------
__global__ void rotary_tables() {
    int idx = blockIdx.x*blockDim.x + threadIdx.x;
    if (idx >= S_*64) return;
    int s = idx >> 6, j = idx & 63;
    float inv_freq = powf(10000.0f, -(2.0f*j)/128.0f);
    float pos = (float)s * inv_freq;
    float sb = (2.0f*j + 0.4f*128.0f) / (1.4f*128.0f);
    float power = ((float)s - (float)(S_/2)) / 512.0f;
    float xs = powf(sb, power);
    float c = cosf(pos), sn = sinf(pos);
    g_qc[idx] = c*xs;  g_qs[idx] = sn*xs;
    g_kc[idx] = c/xs;  g_ks[idx] = sn/xs;
}

// ========== fp16 GEMM: C[M,N](f32) = A[M,K] @ B[N,K]^T (+bias) =============
// CTA 128x256, BK=32, 8 warps as 2(m)x4(n), warp tile 64x64.
// smem rows padded to 144B (72 halves): banks g*4+t, conflict-free.
#define ASTG_H (128*72)
#define BSTG_H (256*72)
#define STG_H  (ASTG_H + BSTG_H)
#define G_SMEM (2*STG_H*2)

__global__ __launch_bounds__(256) void gemm_h(
        const __half* __restrict__ A, const __half* __restrict__ Bm,
        float* __restrict__ C, int M, int N, int K,
        const float* __restrict__ bias) {
    extern __shared__ __half smh[];
    int tid = threadIdx.x, wid = tid >> 5, lane = tid & 31;
    int g = lane >> 2, t = lane & 3;
    int wm = (wid & 1)*64, wn = (wid >> 1)*64;
    int m0 = blockIdx.y*128, n0 = blockIdx.x*256;

    float acc[4][8][4];
    #pragma unroll
    for (int i=0;i<4;i++)
        #pragma unroll
        for (int j=0;j<8;j++)
            #pragma unroll
            for (int k=0;k<4;k++) acc[i][j][k]=0.f;

    #define LOAD_TILE(stg, k0) do {                                           \
        __half* sA = smh + (stg)*STG_H;                                       \
        __half* sB = sA + ASTG_H;                                             \
        _Pragma("unroll")                                                     \
        for (int it = 0; it < 2; it++) {                                      \
            int idx = tid + it*256;                                           \
            int r = idx >> 2, c = idx & 3;                                    \
            cpasync16(&sA[r*72 + c*8], &A[(size_t)(m0+r)*K + (k0) + c*8]);    \
        }                                                                     \
        _Pragma("unroll")                                                     \
        for (int it = 0; it < 4; it++) {                                      \
            int idx = tid + it*256;                                           \
            int r = idx >> 2, c = idx & 3;                                    \
            cpasync16(&sB[r*72 + c*8], &Bm[(size_t)(n0+r)*K + (k0) + c*8]);   \
        }                                                                     \
    } while (0)

    LOAD_TILE(0, 0);
    CP_COMMIT();

    int T = K >> 5;
    for (int tt = 0; tt < T; tt++) {
        if (tt+1 < T) {
            LOAD_TILE((tt+1)&1, (tt+1)*32);
            CP_COMMIT();
            CP_WAIT(1);
        } else {
            CP_WAIT(0);
        }
        __syncthreads();
        const __half* As = smh + (tt&1)*STG_H;
        const __half* Bs = As + ASTG_H;
        #pragma unroll
        for (int kb = 0; kb < 2; kb++) {
            unsigned af[4][4], bf[8][2];
            int co = kb*16 + 2*t;
            #pragma unroll
            for (int mf = 0; mf < 4; mf++) {
                int r = wm + mf*16 + g;
                af[mf][0] = *(const unsigned*)&As[r*72 + co];
                af[mf][1] = *(const unsigned*)&As[(r+8)*72 + co];
                af[mf][2] = *(const unsigned*)&As[r*72 + co + 8];
                af[mf][3] = *(const unsigned*)&As[(r+8)*72 + co + 8];
            }
            #pragma unroll
            for (int nf = 0; nf < 8; nf++) {
                int rn = wn + nf*8 + g;
                bf[nf][0] = *(const unsigned*)&Bs[rn*72 + co];
                bf[nf][1] = *(const unsigned*)&Bs[rn*72 + co + 8];
            }
            #pragma unroll
            for (int mf = 0; mf < 4; mf++)
                #pragma unroll
                for (int nf = 0; nf < 8; nf++)
                    mma_h(acc[mf][nf], af[mf], bf[nf]);
        }
        __syncthreads();
    }
    #pragma unroll
    for (int mf = 0; mf < 4; mf++) {
        #pragma unroll
        for (int nf = 0; nf < 8; nf++) {
            int row = m0 + wm + mf*16 + g;
            int col = n0 + wn + nf*8 + 2*t;
            float b0 = bias ? bias[col]   : 0.f;
            float b1 = bias ? bias[col+1] : 0.f;
            *(float2*)&C[(size_t)row*N + col] =
                make_float2(acc[mf][nf][0]+b0, acc[mf][nf][1]+b1);
            *(float2*)&C[(size_t)(row+8)*N + col] =
                make_float2(acc[mf][nf][2]+b0, acc[mf][nf][3]+b1);
        }
    }
    #undef LOAD_TILE
}

// ---------------- rotary apply: Q (stores fp16) ----------------
__global__ void rot_q() {
    int idx = blockIdx.x*blockDim.x + threadIdx.x;   // B*S*H*64
    if (idx >= B_*S_*H_*64) return;
    int d = idx & 63;
    int h = (idx >> 6) & 15;
    int s = (idx >> 10) & (S_-1);
    int b = idx >> 21;
    const float sw = 0.08838834764831845f;  // 128^-0.5
    size_t base = ((size_t)(b*S_+s))*DM_ + h*DH_;
    float x1 = g_qlin[base+d], x2 = g_qlin[base+d+64];
    float c = g_qc[s*64+d], sn = g_qs[s*64+d];
    size_t ob = ((size_t)((b*H_+h)*S_+s))*DH_;
    g_Qh[ob+d]    = __float2half_rn(sw*(x1*c - x2*sn));
    g_Qh[ob+d+64] = __float2half_rn(sw*(x2*c + x1*sn));
}

// ---------------- rotary apply: K (stores fp16) ----------------
__global__ void rot_k() {
    int idx = blockIdx.x*blockDim.x + threadIdx.x;   // B*S*64
    if (idx >= B_*S_*64) return;
    int d = idx & 63;
    int s = (idx >> 6) & (S_-1);
    int b = idx >> 17;
    const float sw = 0.08838834764831845f;
    size_t base = ((size_t)(b*S_+s))*(2*DH_);
    float x1 = g_kvlin[base+d], x2 = g_kvlin[base+d+64];
    float c = g_kc[s*64+d], sn = g_ks[s*64+d];
    size_t ob = ((size_t)(b*S_+s))*DH_;
    g_Kh[ob+d]    = __float2half_rn(sw*(x1*c - x2*sn));
    g_Kh[ob+d+64] = __float2half_rn(sw*(x2*c + x1*sn));
}

// ---------------- V transpose: kvlin[B,S,256](V part) -> g_Vt[B,D,S] fp16 --
__global__ void v_transpose() {
    __shared__ float tile[64][65];
    int bid = blockIdx.x;
    int dt = bid & 1, st = (bid >> 1) & 31, b = bid >> 6;
    int tid = threadIdx.x;
    #pragma unroll
    for (int it = 0; it < 16; it++) {
        int idx = tid + it*256;
        int r = idx >> 6, c = idx & 63;
        tile[r][c] = g_kvlin[((size_t)(b*S_ + st*64 + r))*(2*DH_) + 128 + dt*64 + c];
    }
    __syncthreads();
    #pragma unroll
    for (int it = 0; it < 16; it++) {
        int idx = tid + it*256;
        int r = idx >> 6, c = idx & 63;
        g_Vt[((size_t)(b*DH_ + dt*64 + r))*S_ + st*64 + c] = __float2half_rn(tile[c][r]);
    }
}

// ---------------- flash attention (fp16 mma, P in registers) ---------------
// BQ=128, BKV=64, D=128. 8 warps; warp w owns q-rows [16w,16w+16).
// smem: 2 stages of (Ks[64 rows x 272B] + Vs[128 rows x 144B]).
#define KS_H (64*136)
#define VS_H (128*72)
#define FSTG_H (KS_H + VS_H)
#define FL_SMEM (2*FSTG_H*2)

__global__ __launch_bounds__(256) void flash_attn() {
    extern __shared__ __half smf[];
    int tid = threadIdx.x;
    int wid = tid >> 5, lane = tid & 31;
    int g = lane >> 2, t = lane & 3;
    int bh = blockIdx.y, b = bh >> 4, h = bh & 15;
    int qt = gridDim.x - 1 - blockIdx.x;   // longest work first
    int q0 = qt * 128;
    int wrow = wid * 16;
    const __half* Qb  = g_Qh + (size_t)bh * S_ * DH_;
    const __half* Kb  = g_Kh + (size_t)b  * S_ * DH_;
    const __half* Vtb = g_Vt + (size_t)b  * DH_ * S_;

    // Q as persistent fp16 A-fragments (8 ksteps of 16)
    unsigned qa[8][4];
    {
        int r0 = q0 + wrow + g;
        #pragma unroll
        for (int kb = 0; kb < 8; kb++) {
            int c0 = kb*16 + 2*t;
            qa[kb][0] = *(const unsigned*)&Qb[(size_t)r0*DH_ + c0];
            qa[kb][1] = *(const unsigned*)&Qb[(size_t)(r0+8)*DH_ + c0];
            qa[kb][2] = *(const unsigned*)&Qb[(size_t)r0*DH_ + c0 + 8];
            qa[kb][3] = *(const unsigned*)&Qb[(size_t)(r0+8)*DH_ + c0 + 8];
        }
    }
    float oacc[16][4];
    #pragma unroll
    for (int i=0;i<16;i++)
        #pragma unroll
        for (int j=0;j<4;j++) oacc[i][j]=0.f;
    float mrow[2] = {-1e30f,-1e30f}, lrow[2] = {0.f,0.f};

    int ntiles = 2*qt + 2;
    #define LOAD_KV(stg, j0) do {                                             \
        __half* Ks_ = smf + (stg)*FSTG_H;                                     \
        __half* Vs_ = Ks_ + KS_H;                                             \
        _Pragma("unroll")                                                     \
        for (int it = 0; it < 4; it++) {                                      \
            int idx = tid + it*256;                                           \
            int r = idx >> 4, c = idx & 15;                                   \
            cpasync16(&Ks_[r*136 + c*8], &Kb[(size_t)((j0)+r)*DH_ + c*8]);    \
        }                                                                     \
        _Pragma("unroll")                                                     \
        for (int it = 0; it < 4; it++) {                                      \
            int idx = tid + it*256;                                           \
            int r = idx >> 3, c = idx & 7;                                    \
            cpasync16(&Vs_[r*72 + c*8], &Vtb[(size_t)r*S_ + (j0) + c*8]);     \
        }                                                                     \
    } while (0)

    LOAD_KV(0, 0);
    CP_COMMIT();

    for (int kt = 0; kt < ntiles; kt++) {
        if (kt+1 < ntiles) {
            LOAD_KV((kt+1)&1, (kt+1)*64);
            CP_COMMIT();
            CP_WAIT(1);
        } else {
            CP_WAIT(0);
        }
        __syncthreads();
        const __half* Ks = smf + (kt&1)*FSTG_H;
        const __half* Vs = Ks + KS_H;
        int j0 = kt * 64;

        // S = Q @ K^T : warp computes 16x64
        float s[8][4];
        #pragma unroll
        for (int i=0;i<8;i++)
            #pragma unroll
            for (int j=0;j<4;j++) s[i][j]=0.f;
        #pragma unroll
        for (int kb = 0; kb < 8; kb++) {
            int co = kb*16 + 2*t;
            #pragma unroll
            for (int nf = 0; nf < 8; nf++) {
                unsigned bfr[2];
                bfr[0] = *(const unsigned*)&Ks[(nf*8+g)*136 + co];
                bfr[1] = *(const unsigned*)&Ks[(nf*8+g)*136 + co + 8];
                mma_h(s[nf], qa[kb], bfr);
            }
        }
        // causal mask
        if (j0 + 63 > q0 + wrow) {
            int r0 = q0 + wrow + g;
            #pragma unroll
            for (int nf = 0; nf < 8; nf++) {
                int c0 = j0 + nf*8 + 2*t;
                if (c0   > r0)   s[nf][0] = -1e30f;
                if (c0+1 > r0)   s[nf][1] = -1e30f;
                if (c0   > r0+8) s[nf][2] = -1e30f;
                if (c0+1 > r0+8) s[nf][3] = -1e30f;
            }
        }
        // online softmax (warp-local quad reductions)
        #pragma unroll
        for (int rr = 0; rr < 2; rr++) {
            float mx = -1e30f;
            #pragma unroll
            for (int nf = 0; nf < 8; nf++)
                mx = fmaxf(mx, fmaxf(s[nf][2*rr], s[nf][2*rr+1]));
            mx = fmaxf(mx, __shfl_xor_sync(0xffffffffu, mx, 1));
            mx = fmaxf(mx, __shfl_xor_sync(0xffffffffu, mx, 2));
            float mn = fmaxf(mrow[rr], mx);
            float corr = __expf(mrow[rr] - mn);
            mrow[rr] = mn;
            float rs = 0.f;
            #pragma unroll
            for (int nf = 0; nf < 8; nf++) {
                float e0 = __expf(s[nf][2*rr]   - mn);
                float e1 = __expf(s[nf][2*rr+1] - mn);
                s[nf][2*rr] = e0; s[nf][2*rr+1] = e1;
                rs += e0 + e1;
            }
            rs += __shfl_xor_sync(0xffffffffu, rs, 1);
            rs += __shfl_xor_sync(0xffffffffu, rs, 2);
            lrow[rr] = lrow[rr]*corr + rs;
            #pragma unroll
            for (int nf = 0; nf < 16; nf++) {
                oacc[nf][2*rr]   *= corr;
                oacc[nf][2*rr+1] *= corr;
            }
        }
        // O += P @ V   (P converted to A-fragments in registers)
        #pragma unroll
        for (int kb2 = 0; kb2 < 4; kb2++) {
            unsigned pa[4];
            pa[0] = packh2(s[2*kb2][0],   s[2*kb2][1]);
            pa[1] = packh2(s[2*kb2][2],   s[2*kb2][3]);
            pa[2] = packh2(s[2*kb2+1][0], s[2*kb2+1][1]);
            pa[3] = packh2(s[2*kb2+1][2], s[2*kb2+1][3]);
            int co = kb2*16 + 2*t;
            #pragma unroll
            for (int nf = 0; nf < 16; nf++) {
                unsigned bfr[2];
                bfr[0] = *(const unsigned*)&Vs[(nf*8+g)*72 + co];
                bfr[1] = *(const unsigned*)&Vs[(nf*8+g)*72 + co + 8];
                mma_h(oacc[nf], pa, bfr);
            }
        }
        __syncthreads();
    }
    // write ctx as fp16 (feeds proj GEMM)
    #pragma unroll
    for (int rr = 0; rr < 2; rr++) {
        float inv = 1.f / lrow[rr];
        int row = q0 + wrow + g + 8*rr;
        size_t base = ((size_t)(b*S_ + row))*DM_ + h*DH_;
        #pragma unroll
        for (int nf = 0; nf < 16; nf++) {
            __half2 hv = __floats2half2_rn(oacc[nf][2*rr]*inv, oacc[nf][2*rr+1]*inv);
            *(__half2*)&g_ctxh[base + nf*8 + 2*t] = hv;
        }
    }
    #undef LOAD_KV
}

// ---------------- launch ----------------
extern "C" void kernel_launch(void* const* d_in, const int* in_sizes, int n_in,
                              void* d_out, int out_size) {
    const float* X     = (const float*)d_in[0];
    const float* Wq    = (const float*)d_in[1];
    const float* Wkv   = (const float*)d_in[2];
    const float* Wproj = (const float*)d_in[3];
    const float* bproj = (const float*)d_in[4];
    float* out = (float*)d_out;

    static int attr_set = 0;
    if (!attr_set) {
        cudaFuncSetAttribute(flash_attn, cudaFuncAttributeMaxDynamicSharedMemorySize, FL_SMEM);
        cudaFuncSetAttribute(gemm_h,     cudaFuncAttributeMaxDynamicSharedMemorySize, G_SMEM);
        attr_set = 1;
    }

    __half* xh;   cudaGetSymbolAddress((void**)&xh,   g_Xh);
    __half* wqh;  cudaGetSymbolAddress((void**)&wqh,  g_Wqh);
    __half* wkvh; cudaGetSymbolAddress((void**)&wkvh, g_Wkvh);
    __half* wph;  cudaGetSymbolAddress((void**)&wph,  g_Wph);
    __half* ctxh; cudaGetSymbolAddress((void**)&ctxh, g_ctxh);
    float* qlin;  cudaGetSymbolAddress((void**)&qlin,  g_qlin);
    float* kvlin; cudaGetSymbolAddress((void**)&kvlin, g_kvlin);

    const int M = B_*S_;   // 4096

    cvt_half<<<(B_*S_*DM_/4+1023)/1024, 256>>>((const float4*)X,     (__half2*)xh,   B_*S_*DM_/4);
    cvt_half<<<(DM_*DM_/4+1023)/1024,   256>>>((const float4*)Wq,    (__half2*)wqh,  DM_*DM_/4);
    cvt_half<<<(2*DH_*DM_/4+1023)/1024, 256>>>((const float4*)Wkv,   (__half2*)wkvh, 2*DH_*DM_/4);
    cvt_half<<<(DM_*DM_/4+1023)/1024,   256>>>((const float4*)Wproj, (__half2*)wph,  DM_*DM_/4);
    rotary_tables<<<(S_*64+255)/256, 256>>>();

    gemm_h<<<dim3(DM_/256,   M/128), 256, G_SMEM>>>(xh, wqh,  qlin,  M, DM_,   DM_, nullptr);
    gemm_h<<<dim3(2*DH_/256, M/128), 256, G_SMEM>>>(xh, wkvh, kvlin, M, 2*DH_, DM_, nullptr);
    rot_q<<<(B_*S_*H_*64+255)/256, 256>>>();
    rot_k<<<(B_*S_*64+255)/256,    256>>>();
    v_transpose<<<B_*32*2, 256>>>();
    flash_attn<<<dim3(S_/128, B_*H_), 256, FL_SMEM>>>();
    gemm_h<<<dim3(DM_/256, M/128), 256, G_SMEM>>>(ctxh, wph, out, M, DM_, DM_, bproj);
}

// round 6
// speedup vs baseline: 10.6243x; 1.1679x over previous
#include <cuda_runtime.h>
#include <cuda_fp16.h>
#include <math.h>
#include <stdint.h>

#define B_  2
#define S_  2048
#define DM_ 2048
#define H_  16
#define DH_ 128
#define NQKV 2304   // 2048 q + 128 k + 128 v

// ---------------- scratch (device globals: allocation-free) ----------------
__device__ __half g_Xh[B_*S_*DM_];
__device__ __half g_Wqkvh[NQKV*DM_];       // rows: 0..2047 Wq, 2048..2175 Wk, 2176..2303 Wv
__device__ __half g_Wph[DM_*DM_];
__device__ float  g_qkvlin[B_*S_*NQKV];    // [B*S, 2304]
__device__ __half g_Qh[B_*H_*S_*DH_];      // [B,H,S,D]  (scaled by sw*log2e)
__device__ __half g_Kh[B_*S_*DH_];         // [B,S,D]    (scaled by sw)
__device__ __half g_Vt[B_*DH_*S_];         // [B,D,S]
__device__ __half g_ctxh[B_*S_*DM_];
__device__ float  g_qc[S_*64], g_qs[S_*64], g_kc[S_*64], g_ks[S_*64];

// ---------------- helpers ----------------
__device__ __forceinline__ void mma_h(float c[4], const unsigned a[4], const unsigned b[2]) {
    asm volatile(
        "mma.sync.aligned.m16n8k16.row.col.f32.f16.f16.f32 "
        "{%0,%1,%2,%3},{%4,%5,%6,%7},{%8,%9},{%0,%1,%2,%3};"
        : "+f"(c[0]), "+f"(c[1]), "+f"(c[2]), "+f"(c[3])
        : "r"(a[0]), "r"(a[1]), "r"(a[2]), "r"(a[3]), "r"(b[0]), "r"(b[1]));
}
__device__ __forceinline__ void cpasync16(void* s, const void* g) {
    unsigned sa = (unsigned)__cvta_generic_to_shared(s);
    asm volatile("cp.async.cg.shared.global [%0], [%1], 16;" :: "r"(sa), "l"(g));
}
#define CP_COMMIT() asm volatile("cp.async.commit_group;" ::: "memory")
#define CP_WAIT(n)  asm volatile("cp.async.wait_group %0;" :: "n"(n) : "memory")
__device__ __forceinline__ unsigned packh2(float x, float y) {
    __half2 h = __floats2half2_rn(x, y);
    return *(unsigned*)&h;
}

// ---------------- fp32 -> fp16 convert ----------------
__global__ void cvt_half(const float4* __restrict__ src, __half2* __restrict__ dst, int n4) {
    int i = blockIdx.x*1024 + threadIdx.x;
    #pragma unroll
    for (int k = 0; k < 4; k++) {
        int j = i + k*256;
        if (j < n4) {
            float4 v = src[j];
            dst[2*j]   = __floats2half2_rn(v.x, v.y);
            dst[2*j+1] = __floats2half2_rn(v.z, v.w);
        }
    }
}

// ---------------- rotary tables ----------------
__global__ void rotary_tables() {
    int idx = blockIdx.x*blockDim.x + threadIdx.x;
    if (idx >= S_*64) return;
    int s = idx >> 6, j = idx & 63;
    float inv_freq = powf(10000.0f, -(2.0f*j)/128.0f);
    float pos = (float)s * inv_freq;
    float sb = (2.0f*j + 0.4f*128.0f) / (1.4f*128.0f);
    float power = ((float)s - (float)(S_/2)) / 512.0f;
    float xs = powf(sb, power);
    float c = cosf(pos), sn = sinf(pos);
    g_qc[idx] = c*xs;  g_qs[idx] = sn*xs;
    g_kc[idx] = c/xs;  g_ks[idx] = sn/xs;
}

// ========== fp16 GEMM: C[M,N](f32) = A[M,K] @ B[N,K]^T (+bias) =============
// CTA 128x256, BK=32, 8 warps as 2(m)x4(n), warp tile 64x64. 3-stage cp.async.
#define ASTG_H (128*72)
#define BSTG_H (256*72)
#define STG_H  (ASTG_H + BSTG_H)
#define G_SMEM (3*STG_H*2)

__global__ __launch_bounds__(256) void gemm_h(
        const __half* __restrict__ A, const __half* __restrict__ Bm,
        float* __restrict__ C, int M, int N, int K,
        const float* __restrict__ bias) {
    extern __shared__ __half smh[];
    int tid = threadIdx.x, wid = tid >> 5, lane = tid & 31;
    int g = lane >> 2, t = lane & 3;
    int wm = (wid & 1)*64, wn = (wid >> 1)*64;
    int m0 = blockIdx.y*128, n0 = blockIdx.x*256;

    float acc[4][8][4];
    #pragma unroll
    for (int i=0;i<4;i++)
        #pragma unroll
        for (int j=0;j<8;j++)
            #pragma unroll
            for (int k=0;k<4;k++) acc[i][j][k]=0.f;

    #define LOAD_TILE(stg, k0) do {                                           \
        __half* sA = smh + (stg)*STG_H;                                       \
        __half* sB = sA + ASTG_H;                                             \
        _Pragma("unroll")                                                     \
        for (int it = 0; it < 2; it++) {                                      \
            int idx = tid + it*256;                                           \
            int r = idx >> 2, c = idx & 3;                                    \
            cpasync16(&sA[r*72 + c*8], &A[(size_t)(m0+r)*K + (k0) + c*8]);    \
        }                                                                     \
        _Pragma("unroll")                                                     \
        for (int it = 0; it < 4; it++) {                                      \
            int idx = tid + it*256;                                           \
            int r = idx >> 2, c = idx & 3;                                    \
            cpasync16(&sB[r*72 + c*8], &Bm[(size_t)(n0+r)*K + (k0) + c*8]);   \
        }                                                                     \
    } while (0)

    LOAD_TILE(0, 0);  CP_COMMIT();
    LOAD_TILE(1, 32); CP_COMMIT();

    int T = K >> 5;
    int stg = 0;
    for (int tt = 0; tt < T; tt++) {
        if (tt == T-1) { CP_WAIT(0); } else { CP_WAIT(1); }
        __syncthreads();
        if (tt+2 < T) {
            int sn = stg+2; if (sn >= 3) sn -= 3;
            LOAD_TILE(sn, (tt+2)*32);
            CP_COMMIT();
        }
        const __half* As = smh + stg*STG_H;
        const __half* Bs = As + ASTG_H;
        #pragma unroll
        for (int kb = 0; kb < 2; kb++) {
            unsigned af[4][4], bf[8][2];
            int co = kb*16 + 2*t;
            #pragma unroll
            for (int mf = 0; mf < 4; mf++) {
                int r = wm + mf*16 + g;
                af[mf][0] = *(const unsigned*)&As[r*72 + co];
                af[mf][1] = *(const unsigned*)&As[(r+8)*72 + co];
                af[mf][2] = *(const unsigned*)&As[r*72 + co + 8];
                af[mf][3] = *(const unsigned*)&As[(r+8)*72 + co + 8];
            }
            #pragma unroll
            for (int nf = 0; nf < 8; nf++) {
                int rn = wn + nf*8 + g;
                bf[nf][0] = *(const unsigned*)&Bs[rn*72 + co];
                bf[nf][1] = *(const unsigned*)&Bs[rn*72 + co + 8];
            }
            #pragma unroll
            for (int mf = 0; mf < 4; mf++)
                #pragma unroll
                for (int nf = 0; nf < 8; nf++)
                    mma_h(acc[mf][nf], af[mf], bf[nf]);
        }
        if (++stg >= 3) stg = 0;
    }
    #pragma unroll
    for (int mf = 0; mf < 4; mf++) {
        #pragma unroll
        for (int nf = 0; nf < 8; nf++) {
            int row = m0 + wm + mf*16 + g;
            int col = n0 + wn + nf*8 + 2*t;
            float b0 = bias ? bias[col]   : 0.f;
            float b1 = bias ? bias[col+1] : 0.f;
            *(float2*)&C[(size_t)row*N + col] =
                make_float2(acc[mf][nf][0]+b0, acc[mf][nf][1]+b1);
            *(float2*)&C[(size_t)(row+8)*N + col] =
                make_float2(acc[mf][nf][2]+b0, acc[mf][nf][3]+b1);
        }
    }
    #undef LOAD_TILE
}

// ---------------- rotary apply: Q (scaled by sw*log2e, stores fp16) --------
__global__ void rot_q() {
    int idx = blockIdx.x*blockDim.x + threadIdx.x;   // B*S*H*64
    if (idx >= B_*S_*H_*64) return;
    int d = idx & 63;
    int h = (idx >> 6) & 15;
    int s = (idx >> 10) & (S_-1);
    int b = idx >> 21;
    const float sw = 0.08838834764831845f * 1.4426950408889634f;  // 128^-0.5 * log2(e)
    size_t base = ((size_t)(b*S_+s))*NQKV + h*DH_;
    float x1 = g_qkvlin[base+d], x2 = g_qkvlin[base+d+64];
    float c = g_qc[s*64+d], sn = g_qs[s*64+d];
    size_t ob = ((size_t)((b*H_+h)*S_+s))*DH_;
    g_Qh[ob+d]    = __float2half_rn(sw*(x1*c - x2*sn));
    g_Qh[ob+d+64] = __float2half_rn(sw*(x2*c + x1*sn));
}

// ---------------- rotary apply: K (stores fp16) ----------------
__global__ void rot_k() {
    int idx = blockIdx.x*blockDim.x + threadIdx.x;   // B*S*64
    if (idx >= B_*S_*64) return;
    int d = idx & 63;
    int s = (idx >> 6) & (S_-1);
    int b = idx >> 17;
    const float sw = 0.08838834764831845f;
    size_t base = ((size_t)(b*S_+s))*NQKV + 2048;
    float x1 = g_qkvlin[base+d], x2 = g_qkvlin[base+d+64];
    float c = g_kc[s*64+d], sn = g_ks[s*64+d];
    size_t ob = ((size_t)(b*S_+s))*DH_;
    g_Kh[ob+d]    = __float2half_rn(sw*(x1*c - x2*sn));
    g_Kh[ob+d+64] = __float2half_rn(sw*(x2*c + x1*sn));
}

// ---------------- V transpose: qkvlin cols 2176..2303 -> g_Vt[B,D,S] fp16 --
__global__ void v_transpose() {
    __shared__ float tile[64][65];
    int bid = blockIdx.x;
    int dt = bid & 1, st = (bid >> 1) & 31, b = bid >> 6;
    int tid = threadIdx.x;
    #pragma unroll
    for (int it = 0; it < 16; it++) {
        int idx = tid + it*256;
        int r = idx >> 6, c = idx & 63;
        tile[r][c] = g_qkvlin[((size_t)(b*S_ + st*64 + r))*NQKV + 2176 + dt*64 + c];
    }
    __syncthreads();
    #pragma unroll
    for (int it = 0; it < 16; it++) {
        int idx = tid + it*256;
        int r = idx >> 6, c = idx & 63;
        g_Vt[((size_t)(b*DH_ + dt*64 + r))*S_ + st*64 + c] = __float2half_rn(tile[c][r]);
    }
}

// ---------------- flash attention (fp16 mma, BQ=128, BKV=128) --------------
// 8 warps; warp w owns q-rows [16w,16w+16). P stays in registers.
// smem: 2 stages of (Ks[128 x 136h] + Vs[128 x 136h]).
#define KS_H (128*136)
#define VS_H (128*136)
#define FSTG_H (KS_H + VS_H)
#define FL_SMEM (2*FSTG_H*2)

__global__ __launch_bounds__(256) void flash_attn() {
    extern __shared__ __half smf[];
    int tid = threadIdx.x;
    int wid = tid >> 5, lane = tid & 31;
    int g = lane >> 2, t = lane & 3;
    int bh = blockIdx.y, b = bh >> 4, h = bh & 15;
    int qt = gridDim.x - 1 - blockIdx.x;   // longest work first
    int q0 = qt * 128;
    int wrow = wid * 16;
    const __half* Qb  = g_Qh + (size_t)bh * S_ * DH_;
    const __half* Kb  = g_Kh + (size_t)b  * S_ * DH_;
    const __half* Vtb = g_Vt + (size_t)b  * DH_ * S_;

    // Q as persistent fp16 A-fragments (8 ksteps of 16)
    unsigned qa[8][4];
    {
        int r0 = q0 + wrow + g;
        #pragma unroll
        for (int kb = 0; kb < 8; kb++) {
            int c0 = kb*16 + 2*t;
            qa[kb][0] = *(const unsigned*)&Qb[(size_t)r0*DH_ + c0];
            qa[kb][1] = *(const unsigned*)&Qb[(size_t)(r0+8)*DH_ + c0];
            qa[kb][2] = *(const unsigned*)&Qb[(size_t)r0*DH_ + c0 + 8];
            qa[kb][3] = *(const unsigned*)&Qb[(size_t)(r0+8)*DH_ + c0 + 8];
        }
    }
    float oacc[16][4];
    #pragma unroll
    for (int i=0;i<16;i++)
        #pragma unroll
        for (int j=0;j<4;j++) oacc[i][j]=0.f;
    float mrow[2] = {-1e30f,-1e30f}, lrow[2] = {0.f,0.f};

    int ntiles = qt + 1;
    #define LOAD_KV(stg, j0) do {                                             \
        __half* Ks_ = smf + (stg)*FSTG_H;                                     \
        __half* Vs_ = Ks_ + KS_H;                                             \
        _Pragma("unroll")                                                     \
        for (int it = 0; it < 8; it++) {                                      \
            int idx = tid + it*256;                                           \
            int r = idx >> 4, c = idx & 15;                                   \
            cpasync16(&Ks_[r*136 + c*8], &Kb[(size_t)((j0)+r)*DH_ + c*8]);    \
        }                                                                     \
        _Pragma("unroll")                                                     \
        for (int it = 0; it < 8; it++) {                                      \
            int idx = tid + it*256;                                           \
            int r = idx >> 4, c = idx & 15;                                   \
            cpasync16(&Vs_[r*136 + c*8], &Vtb[(size_t)r*S_ + (j0) + c*8]);    \
        }                                                                     \
    } while (0)

    LOAD_KV(0, 0);
    CP_COMMIT();

    for (int kt = 0; kt < ntiles; kt++) {
        if (kt+1 < ntiles) {
            LOAD_KV((kt+1)&1, (kt+1)*128);
            CP_COMMIT();
            CP_WAIT(1);
        } else {
            CP_WAIT(0);
        }
        __syncthreads();
        const __half* Ks = smf + (kt&1)*FSTG_H;
        const __half* Vs = Ks + KS_H;
        int j0 = kt * 128;

        // S = Q @ K^T : warp computes 16x128
        float s[16][4];
        #pragma unroll
        for (int i=0;i<16;i++)
            #pragma unroll
            for (int j=0;j<4;j++) s[i][j]=0.f;
        #pragma unroll
        for (int kb = 0; kb < 8; kb++) {
            int co = kb*16 + 2*t;
            #pragma unroll
            for (int nf = 0; nf < 16; nf++) {
                unsigned bfr[2];
                bfr[0] = *(const unsigned*)&Ks[(nf*8+g)*136 + co];
                bfr[1] = *(const unsigned*)&Ks[(nf*8+g)*136 + co + 8];
                mma_h(s[nf], qa[kb], bfr);
            }
        }
        // causal mask (diagonal tile only: j0 == q0)
        if (kt == ntiles-1) {
            int r0 = q0 + wrow + g;
            #pragma unroll
            for (int nf = 0; nf < 16; nf++) {
                int c0 = j0 + nf*8 + 2*t;
                if (c0   > r0)   s[nf][0] = -1e30f;
                if (c0+1 > r0)   s[nf][1] = -1e30f;
                if (c0   > r0+8) s[nf][2] = -1e30f;
                if (c0+1 > r0+8) s[nf][3] = -1e30f;
            }
        }
        // online softmax in log2 domain (Q pre-scaled by log2e)
        #pragma unroll
        for (int rr = 0; rr < 2; rr++) {
            float mx = -1e30f;
            #pragma unroll
            for (int nf = 0; nf < 16; nf++)
                mx = fmaxf(mx, fmaxf(s[nf][2*rr], s[nf][2*rr+1]));
            mx = fmaxf(mx, __shfl_xor_sync(0xffffffffu, mx, 1));
            mx = fmaxf(mx, __shfl_xor_sync(0xffffffffu, mx, 2));
            float mn = fmaxf(mrow[rr], mx);
            float corr = exp2f(mrow[rr] - mn);
            mrow[rr] = mn;
            float rs = 0.f;
            #pragma unroll
            for (int nf = 0; nf < 16; nf++) {
                float e0 = exp2f(s[nf][2*rr]   - mn);
                float e1 = exp2f(s[nf][2*rr+1] - mn);
                s[nf][2*rr] = e0; s[nf][2*rr+1] = e1;
                rs += e0 + e1;
            }
            rs += __shfl_xor_sync(0xffffffffu, rs, 1);
            rs += __shfl_xor_sync(0xffffffffu, rs, 2);
            lrow[rr] = lrow[rr]*corr + rs;
            #pragma unroll
            for (int nf = 0; nf < 16; nf++) {
                oacc[nf][2*rr]   *= corr;
                oacc[nf][2*rr+1] *= corr;
            }
        }
        // O += P @ V   (P converted to A-fragments in registers)
        #pragma unroll
        for (int kb2 = 0; kb2 < 8; kb2++) {
            unsigned pa[4];
            pa[0] = packh2(s[2*kb2][0],   s[2*kb2][1]);
            pa[1] = packh2(s[2*kb2][2],   s[2*kb2][3]);
            pa[2] = packh2(s[2*kb2+1][0], s[2*kb2+1][1]);
            pa[3] = packh2(s[2*kb2+1][2], s[2*kb2+1][3]);
            int co = kb2*16 + 2*t;
            #pragma unroll
            for (int nf = 0; nf < 16; nf++) {
                unsigned bfr[2];
                bfr[0] = *(const unsigned*)&Vs[(nf*8+g)*136 + co];
                bfr[1] = *(const unsigned*)&Vs[(nf*8+g)*136 + co + 8];
                mma_h(oacc[nf], pa, bfr);
            }
        }
        __syncthreads();
    }
    // write ctx as fp16 (feeds proj GEMM)
    #pragma unroll
    for (int rr = 0; rr < 2; rr++) {
        float inv = 1.f / lrow[rr];
        int row = q0 + wrow + g + 8*rr;
        size_t base = ((size_t)(b*S_ + row))*DM_ + h*DH_;
        #pragma unroll
        for (int nf = 0; nf < 16; nf++) {
            __half2 hv = __floats2half2_rn(oacc[nf][2*rr]*inv, oacc[nf][2*rr+1]*inv);
            *(__half2*)&g_ctxh[base + nf*8 + 2*t] = hv;
        }
    }
    #undef LOAD_KV
}

// ---------------- launch ----------------
extern "C" void kernel_launch(void* const* d_in, const int* in_sizes, int n_in,
                              void* d_out, int out_size) {
    const float* X     = (const float*)d_in[0];
    const float* Wq    = (const float*)d_in[1];
    const float* Wkv   = (const float*)d_in[2];
    const float* Wproj = (const float*)d_in[3];
    const float* bproj = (const float*)d_in[4];
    float* out = (float*)d_out;

    static int attr_set = 0;
    if (!attr_set) {
        cudaFuncSetAttribute(flash_attn, cudaFuncAttributeMaxDynamicSharedMemorySize, FL_SMEM);
        cudaFuncSetAttribute(gemm_h,     cudaFuncAttributeMaxDynamicSharedMemorySize, G_SMEM);
        attr_set = 1;
    }

    __half* xh;    cudaGetSymbolAddress((void**)&xh,    g_Xh);
    __half* wqkvh; cudaGetSymbolAddress((void**)&wqkvh, g_Wqkvh);
    __half* wph;   cudaGetSymbolAddress((void**)&wph,   g_Wph);
    __half* ctxh;  cudaGetSymbolAddress((void**)&ctxh,  g_ctxh);
    float* qkvlin; cudaGetSymbolAddress((void**)&qkvlin, g_qkvlin);

    const int M = B_*S_;   // 4096

    cvt_half<<<(B_*S_*DM_/4+1023)/1024, 256>>>((const float4*)X,     (__half2*)xh, B_*S_*DM_/4);
    cvt_half<<<(DM_*DM_/4+1023)/1024,   256>>>((const float4*)Wq,    (__half2*)wqkvh, DM_*DM_/4);
    cvt_half<<<(2*DH_*DM_/4+1023)/1024, 256>>>((const float4*)Wkv,
                                               (__half2*)(wqkvh + (size_t)DM_*DM_), 2*DH_*DM_/4);
    cvt_half<<<(DM_*DM_/4+1023)/1024,   256>>>((const float4*)Wproj, (__half2*)wph, DM_*DM_/4);
    rotary_tables<<<(S_*64+255)/256, 256>>>();

    gemm_h<<<dim3(NQKV/256, M/128), 256, G_SMEM>>>(xh, wqkvh, qkvlin, M, NQKV, DM_, nullptr);
    rot_q<<<(B_*S_*H_*64+255)/256, 256>>>();
    rot_k<<<(B_*S_*64+255)/256,    256>>>();
    v_transpose<<<B_*32*2, 256>>>();
    flash_attn<<<dim3(S_/128, B_*H_), 256, FL_SMEM>>>();
    gemm_h<<<dim3(DM_/256, M/128), 256, G_SMEM>>>(ctxh, wph, out, M, DM_, DM_, bproj);
}